// round 2
// baseline (speedup 1.0000x reference)
#include <cuda_runtime.h>
#include <cstdint>

// ScaledDotProductAttention: B=2, H=16, S=2048, D=64, temperature=8.0
// out = softmax(mask ? (Q K^T)/8 : finfo.min) V
//
// Flash-attention style fp32 SIMT baseline.
// Grid: (S/BR, B*H) = (32, 32) CTAs, 128 threads each.
// Per CTA: 64 query rows, loop over 32 key tiles of 64.
// Thread (tx, ty): tx = tid&7, ty = tid>>3.
//   Owns rows  ty*4 .. ty*4+3            (4 rows)
//   Owns cols  tx, tx+8, ..., tx+56      (8 strided cols -> conflict-free LDS)

namespace {
constexpr int kS       = 2048;
constexpr int kD       = 64;
constexpr int kBH      = 32;
constexpr int kBR      = 64;
constexpr int kBC      = 64;
constexpr int kThreads = 128;
constexpr int kStride  = kD + 1;   // 65 floats: kills ty-direction bank conflicts
constexpr int kTiles   = kS / kBC; // 32
constexpr float kScale = 0.125f;               // 1 / temperature
constexpr float kNeg   = -3.402823466e38f;     // finfo(float32).min, matches jnp.where fill
constexpr int kSmemFloats = 3 * kBR * kStride; // Q, K(/P), V  -> 12480 floats = 49920 B
}

// minBlocks=3 caps regs at 170 -> guarantees 3 CTAs/SM (12 warps); smem (49.9KB)
// would otherwise allow 4 but unconstrained regalloc risks a 2-CTA cliff.
__global__ void __launch_bounds__(kThreads, 3)
fa_fp32_kernel(const float* __restrict__ gq, const float* __restrict__ gk,
               const float* __restrict__ gv, const int* __restrict__ gmask,
               float* __restrict__ gout)
{
    extern __shared__ float smem[];
    float* sQ = smem;                       // [64][65]
    float* sK = smem + kBR * kStride;       // [64][65], reused as sP after S-GEMM
    float* sV = smem + 2 * kBR * kStride;   // [64][65]
    float* sP = sK;

    const int bh  = blockIdx.y;
    const int q0  = blockIdx.x * kBR;
    const int tid = threadIdx.x;
    const int tx  = tid & 7;
    const int ty  = tid >> 3;
    const int ty4 = ty * 4;

    const float* qb = gq + (size_t)bh * kS * kD;
    const float* kb = gk + (size_t)bh * kS * kD;
    const float* vb = gv + (size_t)bh * kS * kD;

    // ---- Load Q tile (64x64 floats), coalesced float4, scalar smem stores (pad 65) ----
    for (int i = tid; i < kBR * kD / 4; i += kThreads) {
        const int r = i >> 4;               // kD/4 == 16
        const int c = (i & 15) << 2;
        const float4 t = *reinterpret_cast<const float4*>(qb + (size_t)(q0 + r) * kD + c);
        float* dst = sQ + r * kStride + c;
        dst[0] = t.x; dst[1] = t.y; dst[2] = t.z; dst[3] = t.w;
    }

    float mrow[4], lrow[4];
    float accO[4][8];
    #pragma unroll
    for (int i = 0; i < 4; ++i) {
        mrow[i] = kNeg;
        lrow[i] = 0.0f;
        #pragma unroll
        for (int j = 0; j < 8; ++j) accO[i][j] = 0.0f;
    }

    for (int kt = 0; kt < kTiles; ++kt) {
        const int kk0 = kt * kBC;

        __syncthreads();  // previous tile's P/V reads complete before overwriting K/V

        // ---- Load K and V tiles ----
        for (int i = tid; i < kBC * kD / 4; i += kThreads) {
            const int r = i >> 4;
            const int c = (i & 15) << 2;
            const size_t goff = (size_t)(kk0 + r) * kD + c;
            const float4 tk = *reinterpret_cast<const float4*>(kb + goff);
            const float4 tv = *reinterpret_cast<const float4*>(vb + goff);
            float* dk = sK + r * kStride + c;
            float* dv = sV + r * kStride + c;
            dk[0] = tk.x; dk[1] = tk.y; dk[2] = tk.z; dk[3] = tk.w;
            dv[0] = tv.x; dv[1] = tv.y; dv[2] = tv.z; dv[3] = tv.w;
        }
        __syncthreads();

        // ---- Prefetch mask: issued HERE, consumed AFTER the S-GEMM below,
        //      so ~250cyc L2 latency hides under ~4096 cycles of FFMA. ----
        // mask is [1,1,S,S] broadcast; cols are strided: tx + 8j
        int mreg[4][8];
        {
            const int* mb = gmask + (size_t)(q0 + ty4) * kS + kk0 + tx;
            #pragma unroll
            for (int i = 0; i < 4; ++i)
                #pragma unroll
                for (int j = 0; j < 8; ++j)
                    mreg[i][j] = mb[(size_t)i * kS + 8 * j];
        }

        // ---- S = Q K^T  (4x8 register tile per thread) ----
        float sacc[4][8];
        #pragma unroll
        for (int i = 0; i < 4; ++i)
            #pragma unroll
            for (int j = 0; j < 8; ++j) sacc[i][j] = 0.0f;

        #pragma unroll 8
        for (int d = 0; d < kD; ++d) {
            float qv[4], kv[8];
            #pragma unroll
            for (int i = 0; i < 4; ++i) qv[i] = sQ[(ty4 + i) * kStride + d];
            #pragma unroll
            for (int j = 0; j < 8; ++j) kv[j] = sK[(tx + 8 * j) * kStride + d];
            #pragma unroll
            for (int i = 0; i < 4; ++i)
                #pragma unroll
                for (int j = 0; j < 8; ++j)
                    sacc[i][j] = fmaf(qv[i], kv[j], sacc[i][j]);
        }

        // ---- Scale + mask + online softmax update ----
        #pragma unroll
        for (int i = 0; i < 4; ++i) {
            #pragma unroll
            for (int j = 0; j < 8; ++j)
                sacc[i][j] = mreg[i][j] ? sacc[i][j] * kScale : kNeg;

            float mx = sacc[i][0];
            #pragma unroll
            for (int j = 1; j < 8; ++j) mx = fmaxf(mx, sacc[i][j]);
            // row spans 8 consecutive lanes (same ty): butterfly over xor 1,2,4
            mx = fmaxf(mx, __shfl_xor_sync(0xffffffffu, mx, 1));
            mx = fmaxf(mx, __shfl_xor_sync(0xffffffffu, mx, 2));
            mx = fmaxf(mx, __shfl_xor_sync(0xffffffffu, mx, 4));

            const float mnew = fmaxf(mrow[i], mx);
            const float corr = __expf(mrow[i] - mnew);  // NEG-NEG -> exp(0)=1 (all-masked row ok)
            mrow[i] = mnew;

            float rs = 0.0f;
            #pragma unroll
            for (int j = 0; j < 8; ++j) {
                const float p = __expf(sacc[i][j] - mnew);
                sacc[i][j] = p;
                rs += p;
            }
            rs += __shfl_xor_sync(0xffffffffu, rs, 1);
            rs += __shfl_xor_sync(0xffffffffu, rs, 2);
            rs += __shfl_xor_sync(0xffffffffu, rs, 4);

            lrow[i] = lrow[i] * corr + rs;
            #pragma unroll
            for (int j = 0; j < 8; ++j) accO[i][j] *= corr;
        }

        __syncthreads();  // all threads finished reading sK before it becomes sP

        // ---- Stage P into smem (reuses K buffer) ----
        #pragma unroll
        for (int i = 0; i < 4; ++i)
            #pragma unroll
            for (int j = 0; j < 8; ++j)
                sP[(ty4 + i) * kStride + tx + 8 * j] = sacc[i][j];
        __syncthreads();

        // ---- O += P V  (strided cols: dcol = tx + 8j -> conflict-free;
        //      sP row read is a same-address broadcast across the 8 lanes) ----
        #pragma unroll 8
        for (int c = 0; c < kBC; ++c) {
            float pv[4], vv[8];
            #pragma unroll
            for (int i = 0; i < 4; ++i) pv[i] = sP[(ty4 + i) * kStride + c];
            #pragma unroll
            for (int j = 0; j < 8; ++j) vv[j] = sV[c * kStride + tx + 8 * j];
            #pragma unroll
            for (int i = 0; i < 4; ++i)
                #pragma unroll
                for (int j = 0; j < 8; ++j)
                    accO[i][j] = fmaf(pv[i], vv[j], accO[i][j]);
        }
    }

    // ---- Epilogue: normalize and store ----
    float* ob = gout + ((size_t)bh * kS + q0) * kD;
    #pragma unroll
    for (int i = 0; i < 4; ++i) {
        const float inv = 1.0f / lrow[i];
        float* orow = ob + (size_t)(ty4 + i) * kD;
        #pragma unroll
        for (int j = 0; j < 8; ++j)
            orow[tx + 8 * j] = accO[i][j] * inv;
    }
}

extern "C" void kernel_launch(void* const* d_in, const int* in_sizes, int n_in,
                              void* d_out, int out_size) {
    const float* q    = (const float*)d_in[0];
    const float* k    = (const float*)d_in[1];
    const float* v    = (const float*)d_in[2];
    const int*   mask = (const int*)d_in[3];
    float*       out  = (float*)d_out;

    // 49920 B dynamic smem > 48 KB default: opt in every call (idempotent, capture-safe)
    cudaFuncSetAttribute(fa_fp32_kernel,
                         cudaFuncAttributeMaxDynamicSharedMemorySize,
                         kSmemFloats * (int)sizeof(float));

    dim3 grid(kS / kBR, kBH);
    fa_fp32_kernel<<<grid, kThreads, kSmemFloats * sizeof(float)>>>(q, k, v, mask, out);
}

// round 10
// speedup vs baseline: 2.1890x; 2.1890x over previous
#include <cuda_runtime.h>
#include <cuda_bf16.h>
#include <cstdint>

// ScaledDotProductAttention B=2,H=16,S=2048,D=64, temp=8.
// Flash attention on the tensor pipe via mma.sync.m16n8k16 (bf16, sm_80+ ISA —
// compiles on plain sm_103; tcgen05 is rejected by this harness's ptxas target).
// fp32 accuracy via hi/lo bf16 split: S = QhKh+QhKl+QlKh ; PV = PhVh+PhVl+PlVh.
// Grid (32,32), 128 threads. Warp w owns query rows w*16..w*16+15.
// P stays in registers: S C-fragment layout == PV A-fragment layout.

namespace {
constexpr int kS = 2048, kD = 64;
constexpr int kBH = 32;
constexpr int kBR = 64, kBC = 64;
constexpr int kThreads = 128;
constexpr int kTiles = kS / kBC;      // 32
constexpr float kScale = 0.125f;
constexpr float kNeg = -3.402823466e38f;   // finfo(float32).min
constexpr int kStr = 72;              // smem row stride in bf16 (144B): B-frag LDS conflict-free
}

__device__ __forceinline__ uint32_t pack_bf16(float lo, float hi) {
    uint32_t r;
    asm("cvt.rn.bf16x2.f32 %0, %1, %2;" : "=r"(r) : "f"(hi), "f"(lo));
    return r;
}

// hi/lo split of two floats into packed bf16x2 regs (hi = rn(x), lo = rn(x - hi))
__device__ __forceinline__ void split2(float x, float y, uint32_t& h, uint32_t& l) {
    const float hx = __bfloat162float(__float2bfloat16(x));
    const float hy = __bfloat162float(__float2bfloat16(y));
    h = pack_bf16(x, y);
    l = pack_bf16(x - hx, y - hy);
}

__device__ __forceinline__ void mma16816(float* c, const uint32_t* a, uint32_t b0, uint32_t b1) {
    asm volatile(
        "mma.sync.aligned.m16n8k16.row.col.f32.bf16.bf16.f32 "
        "{%0,%1,%2,%3}, {%4,%5,%6,%7}, {%8,%9}, {%0,%1,%2,%3};"
        : "+f"(c[0]), "+f"(c[1]), "+f"(c[2]), "+f"(c[3])
        : "r"(a[0]), "r"(a[1]), "r"(a[2]), "r"(a[3]), "r"(b0), "r"(b1));
}

__global__ void __launch_bounds__(kThreads, 3)
fa_hmma_kernel(const float* __restrict__ gq, const float* __restrict__ gk,
               const float* __restrict__ gv, const int* __restrict__ gmask,
               float* __restrict__ gout)
{
    // K and V tiles, hi/lo bf16, natural [key][d] layout, rows padded to 72 elems.
    __shared__ unsigned short sKh[kBC * kStr], sKl[kBC * kStr];
    __shared__ unsigned short sVh[kBC * kStr], sVl[kBC * kStr];

    const int tid  = threadIdx.x;
    const int w    = tid >> 5;
    const int lane = tid & 31;
    const int g    = lane >> 2;     // fragment row group 0..7
    const int q    = lane & 3;      // fragment col pair 0..3
    const int bh   = blockIdx.y;
    const int q0   = blockIdx.x * kBR;

    const float* qb = gq + (size_t)bh * kS * kD;
    const float* kb = gk + (size_t)bh * kS * kD;
    const float* vb = gv + (size_t)bh * kS * kD;

    const int row0 = q0 + w * 16 + g;   // this thread's two query rows
    const int row1 = row0 + 8;

    // ---- Q fragments (hi/lo), resident in registers for all 32 tiles ----
    // a0:(row0, d0..d0+1) a1:(row1, d0..) a2:(row0, d0+8..) a3:(row1, d0+8..)
    uint32_t qh[4][4], ql[4][4];
    #pragma unroll
    for (int kblk = 0; kblk < 4; ++kblk) {
        const int d0 = kblk * 16 + q * 2;
        const float2 x0 = *reinterpret_cast<const float2*>(qb + (size_t)row0 * kD + d0);
        const float2 x1 = *reinterpret_cast<const float2*>(qb + (size_t)row1 * kD + d0);
        const float2 x2 = *reinterpret_cast<const float2*>(qb + (size_t)row0 * kD + d0 + 8);
        const float2 x3 = *reinterpret_cast<const float2*>(qb + (size_t)row1 * kD + d0 + 8);
        split2(x0.x, x0.y, qh[kblk][0], ql[kblk][0]);
        split2(x1.x, x1.y, qh[kblk][1], ql[kblk][1]);
        split2(x2.x, x2.y, qh[kblk][2], ql[kblk][2]);
        split2(x3.x, x3.y, qh[kblk][3], ql[kblk][3]);
    }

    float m0 = kNeg, m1 = kNeg, l0 = 0.0f, l1 = 0.0f;
    float acco[8][4];
    #pragma unroll
    for (int nb = 0; nb < 8; ++nb)
        #pragma unroll
        for (int j = 0; j < 4; ++j) acco[nb][j] = 0.0f;

    for (int kt = 0; kt < kTiles; ++kt) {
        const int kk0 = kt * kBC;

        __syncthreads();   // previous tile's MMAs done reading smem

        // ---- Convert K,V tile -> hi/lo bf16 smem (coalesced float4 loads) ----
        for (int i = tid; i < kBC * kD / 4; i += kThreads) {
            const int r = i >> 4;              // key
            const int c = (i & 15) << 2;       // d
            const size_t gg = (size_t)(kk0 + r) * kD + c;
            const float4 tk = *reinterpret_cast<const float4*>(kb + gg);
            const float4 tv = *reinterpret_cast<const float4*>(vb + gg);
            uint32_t h, l;
            const int e = r * kStr + c;
            split2(tk.x, tk.y, h, l);
            *reinterpret_cast<uint32_t*>(&sKh[e]) = h;
            *reinterpret_cast<uint32_t*>(&sKl[e]) = l;
            split2(tk.z, tk.w, h, l);
            *reinterpret_cast<uint32_t*>(&sKh[e + 2]) = h;
            *reinterpret_cast<uint32_t*>(&sKl[e + 2]) = l;
            split2(tv.x, tv.y, h, l);
            *reinterpret_cast<uint32_t*>(&sVh[e]) = h;
            *reinterpret_cast<uint32_t*>(&sVl[e]) = l;
            split2(tv.z, tv.w, h, l);
            *reinterpret_cast<uint32_t*>(&sVh[e + 2]) = h;
            *reinterpret_cast<uint32_t*>(&sVl[e + 2]) = l;
        }
        __syncthreads();

        // ---- Mask bits for both rows (LDG issues early, consumed post-MMA) ----
        uint32_t bits0 = 0, bits1 = 0;
        {
            const int* mp0 = gmask + (size_t)row0 * kS + kk0 + q * 2;
            const int* mp1 = gmask + (size_t)row1 * kS + kk0 + q * 2;
            #pragma unroll
            for (int nb = 0; nb < 8; ++nb) {
                const int2 a = *reinterpret_cast<const int2*>(mp0 + nb * 8);
                const int2 b = *reinterpret_cast<const int2*>(mp1 + nb * 8);
                bits0 |= ((a.x != 0) ? 1u : 0u) << (2 * nb);
                bits0 |= ((a.y != 0) ? 1u : 0u) << (2 * nb + 1);
                bits1 |= ((b.x != 0) ? 1u : 0u) << (2 * nb);
                bits1 |= ((b.y != 0) ? 1u : 0u) << (2 * nb + 1);
            }
        }

        // ---- S = Q K^T (3-term split). B-frag: n=key, k=d. ----
        float sacc[8][4];
        #pragma unroll
        for (int nb = 0; nb < 8; ++nb)
            #pragma unroll
            for (int j = 0; j < 4; ++j) sacc[nb][j] = 0.0f;

        #pragma unroll
        for (int kblk = 0; kblk < 4; ++kblk) {
            const int d0 = kblk * 16 + q * 2;
            #pragma unroll
            for (int nb = 0; nb < 8; ++nb) {
                const int key = nb * 8 + g;
                const int e = key * kStr + d0;
                const uint32_t bh0 = *reinterpret_cast<const uint32_t*>(&sKh[e]);
                const uint32_t bh1 = *reinterpret_cast<const uint32_t*>(&sKh[e + 8]);
                const uint32_t bl0 = *reinterpret_cast<const uint32_t*>(&sKl[e]);
                const uint32_t bl1 = *reinterpret_cast<const uint32_t*>(&sKl[e + 8]);
                mma16816(sacc[nb], qh[kblk], bh0, bh1);
                mma16816(sacc[nb], qh[kblk], bl0, bl1);
                mma16816(sacc[nb], ql[kblk], bh0, bh1);
            }
        }

        // ---- Scale + mask + online softmax (rows row0: j=0,1 / row1: j=2,3) ----
        float sv[8][4];
        #pragma unroll
        for (int nb = 0; nb < 8; ++nb) {
            sv[nb][0] = ((bits0 >> (2 * nb)) & 1u)     ? sacc[nb][0] * kScale : kNeg;
            sv[nb][1] = ((bits0 >> (2 * nb + 1)) & 1u) ? sacc[nb][1] * kScale : kNeg;
            sv[nb][2] = ((bits1 >> (2 * nb)) & 1u)     ? sacc[nb][2] * kScale : kNeg;
            sv[nb][3] = ((bits1 >> (2 * nb + 1)) & 1u) ? sacc[nb][3] * kScale : kNeg;
        }
        float mx0 = sv[0][0], mx1 = sv[0][2];
        #pragma unroll
        for (int nb = 0; nb < 8; ++nb) {
            mx0 = fmaxf(mx0, fmaxf(sv[nb][0], sv[nb][1]));
            mx1 = fmaxf(mx1, fmaxf(sv[nb][2], sv[nb][3]));
        }
        mx0 = fmaxf(mx0, __shfl_xor_sync(0xffffffffu, mx0, 1));
        mx0 = fmaxf(mx0, __shfl_xor_sync(0xffffffffu, mx0, 2));
        mx1 = fmaxf(mx1, __shfl_xor_sync(0xffffffffu, mx1, 1));
        mx1 = fmaxf(mx1, __shfl_xor_sync(0xffffffffu, mx1, 2));

        const float mn0 = fmaxf(m0, mx0);
        const float mn1 = fmaxf(m1, mx1);
        const float corr0 = __expf(m0 - mn0);   // kNeg-kNeg -> exp(0)=1 (all-masked ok)
        const float corr1 = __expf(m1 - mn1);
        m0 = mn0; m1 = mn1;

        float rs0 = 0.0f, rs1 = 0.0f;
        #pragma unroll
        for (int nb = 0; nb < 8; ++nb) {
            sv[nb][0] = __expf(sv[nb][0] - m0); rs0 += sv[nb][0];
            sv[nb][1] = __expf(sv[nb][1] - m0); rs0 += sv[nb][1];
            sv[nb][2] = __expf(sv[nb][2] - m1); rs1 += sv[nb][2];
            sv[nb][3] = __expf(sv[nb][3] - m1); rs1 += sv[nb][3];
        }
        rs0 += __shfl_xor_sync(0xffffffffu, rs0, 1);
        rs0 += __shfl_xor_sync(0xffffffffu, rs0, 2);
        rs1 += __shfl_xor_sync(0xffffffffu, rs1, 1);
        rs1 += __shfl_xor_sync(0xffffffffu, rs1, 2);
        l0 = l0 * corr0 + rs0;
        l1 = l1 * corr1 + rs1;
        #pragma unroll
        for (int nb = 0; nb < 8; ++nb) {
            acco[nb][0] *= corr0; acco[nb][1] *= corr0;
            acco[nb][2] *= corr1; acco[nb][3] *= corr1;
        }

        // ---- P fragments (register-resident): A-frag kb from C-frags nb=2kb,2kb+1 ----
        uint32_t ph[4][4], pl[4][4];
        #pragma unroll
        for (int kblk = 0; kblk < 4; ++kblk) {
            split2(sv[2 * kblk][0],     sv[2 * kblk][1],     ph[kblk][0], pl[kblk][0]);
            split2(sv[2 * kblk][2],     sv[2 * kblk][3],     ph[kblk][1], pl[kblk][1]);
            split2(sv[2 * kblk + 1][0], sv[2 * kblk + 1][1], ph[kblk][2], pl[kblk][2]);
            split2(sv[2 * kblk + 1][2], sv[2 * kblk + 1][3], ph[kblk][3], pl[kblk][3]);
        }

        // ---- O += P V (3-term split). B-frag: n=d, k=key; V is [key][d] so
        //      pack two LDS16 (rows key, key+1 at col d) into one bf16x2 reg. ----
        #pragma unroll
        for (int kblk = 0; kblk < 4; ++kblk) {
            const int key0 = kblk * 16 + q * 2;
            #pragma unroll
            for (int nb = 0; nb < 8; ++nb) {
                const int d = nb * 8 + g;
                const int e0 = key0 * kStr + d;
                const uint32_t vh0 = (uint32_t)sVh[e0] | ((uint32_t)sVh[e0 + kStr] << 16);
                const uint32_t vh1 = (uint32_t)sVh[e0 + 8 * kStr] | ((uint32_t)sVh[e0 + 9 * kStr] << 16);
                const uint32_t vl0 = (uint32_t)sVl[e0] | ((uint32_t)sVl[e0 + kStr] << 16);
                const uint32_t vl1 = (uint32_t)sVl[e0 + 8 * kStr] | ((uint32_t)sVl[e0 + 9 * kStr] << 16);
                mma16816(acco[nb], ph[kblk], vh0, vh1);
                mma16816(acco[nb], ph[kblk], vl0, vl1);
                mma16816(acco[nb], pl[kblk], vh0, vh1);
            }
        }
    }

    // ---- Epilogue: normalize, store (cols nb*8 + q*2 + {0,1}) ----
    const float inv0 = 1.0f / l0;
    const float inv1 = 1.0f / l1;
    float* o0 = gout + ((size_t)bh * kS + row0) * kD;
    float* o1 = gout + ((size_t)bh * kS + row1) * kD;
    #pragma unroll
    for (int nb = 0; nb < 8; ++nb) {
        const int c = nb * 8 + q * 2;
        float2 t0; t0.x = acco[nb][0] * inv0; t0.y = acco[nb][1] * inv0;
        float2 t1; t1.x = acco[nb][2] * inv1; t1.y = acco[nb][3] * inv1;
        *reinterpret_cast<float2*>(o0 + c) = t0;
        *reinterpret_cast<float2*>(o1 + c) = t1;
    }
}

extern "C" void kernel_launch(void* const* d_in, const int* in_sizes, int n_in,
                              void* d_out, int out_size) {
    const float* q    = (const float*)d_in[0];
    const float* k    = (const float*)d_in[1];
    const float* v    = (const float*)d_in[2];
    const int*   mask = (const int*)d_in[3];
    float*       out  = (float*)d_out;

    dim3 grid(kS / kBR, kBH);
    fa_hmma_kernel<<<grid, kThreads>>>(q, k, v, mask, out);
}